// round 5
// baseline (speedup 1.0000x reference)
#include <cuda_runtime.h>
#include <cstdint>

#define MAX_SEG  131072
#define MAX_ROWS 4505600

// Scratch (no allocations allowed -> __device__ globals)
__device__ unsigned g_counts[MAX_SEG];     // per-segment row count
__device__ unsigned g_offs_tmp[MAX_SEG];   // per-block-local exclusive scan
__device__ unsigned g_blk_sums[256];       // per-scan-block totals
__device__ unsigned g_blk_off[256];        // scanned block totals
__device__ unsigned g_offsets[MAX_SEG];    // final exclusive offsets
__device__ unsigned g_cursor[MAX_SEG];     // mutable placement cursors
__device__ int      g_rows[MAX_ROWS];      // row ids sorted by segment

// ---------------------------------------------------------------------------
// 1: zero counts
// ---------------------------------------------------------------------------
__global__ void zero_counts(int n_seg) {
    int i = blockIdx.x * blockDim.x + threadIdx.x;
    if (i < n_seg) g_counts[i] = 0u;
}

// ---------------------------------------------------------------------------
// 2: histogram of segment ids (RED, no return value needed)
// ---------------------------------------------------------------------------
__global__ void hist_kernel(const int* __restrict__ index, int n_rows) {
    int i = blockIdx.x * blockDim.x + threadIdx.x;
    if (i < n_rows) atomicAdd(&g_counts[index[i]], 1u);
}

// ---------------------------------------------------------------------------
// 3: per-block exclusive scan (1024 counts per block, 256 threads x 4)
// ---------------------------------------------------------------------------
__global__ void scan_blocks(int n_seg) {
    __shared__ unsigned s[256];
    int b = blockIdx.x, t = threadIdx.x;
    int base = b * 1024 + t * 4;
    unsigned v0 = 0, v1 = 0, v2 = 0, v3 = 0;
    if (base + 0 < n_seg) v0 = g_counts[base + 0];
    if (base + 1 < n_seg) v1 = g_counts[base + 1];
    if (base + 2 < n_seg) v2 = g_counts[base + 2];
    if (base + 3 < n_seg) v3 = g_counts[base + 3];
    unsigned tsum = v0 + v1 + v2 + v3;
    s[t] = tsum;
    __syncthreads();
    for (int d = 1; d < 256; d <<= 1) {           // Hillis-Steele inclusive
        unsigned add = (t >= d) ? s[t - d] : 0u;
        __syncthreads();
        s[t] += add;
        __syncthreads();
    }
    unsigned excl = s[t] - tsum;
    if (base + 0 < n_seg) g_offs_tmp[base + 0] = excl;
    if (base + 1 < n_seg) g_offs_tmp[base + 1] = excl + v0;
    if (base + 2 < n_seg) g_offs_tmp[base + 2] = excl + v0 + v1;
    if (base + 3 < n_seg) g_offs_tmp[base + 3] = excl + v0 + v1 + v2;
    if (t == 255) g_blk_sums[b] = s[255];
}

// ---------------------------------------------------------------------------
// 4: scan the block totals (single block, nblk <= 256)
// ---------------------------------------------------------------------------
__global__ void scan_top(int nblk) {
    __shared__ unsigned s[256];
    int t = threadIdx.x;
    unsigned v = (t < nblk) ? g_blk_sums[t] : 0u;
    s[t] = v;
    __syncthreads();
    for (int d = 1; d < 256; d <<= 1) {
        unsigned add = (t >= d) ? s[t - d] : 0u;
        __syncthreads();
        s[t] += add;
        __syncthreads();
    }
    if (t < nblk) g_blk_off[t] = s[t] - v;
}

// ---------------------------------------------------------------------------
// 5: final offsets + cursor init
// ---------------------------------------------------------------------------
__global__ void finalize_offsets(int n_seg) {
    int i = blockIdx.x * blockDim.x + threadIdx.x;
    if (i < n_seg) {
        unsigned o = g_offs_tmp[i] + g_blk_off[i >> 10];
        g_offsets[i] = o;
        g_cursor[i]  = o;
    }
}

// ---------------------------------------------------------------------------
// 6: place each row id into its segment's slot
// ---------------------------------------------------------------------------
__global__ void build_rows(const int* __restrict__ index, int n_rows) {
    int i = blockIdx.x * blockDim.x + threadIdx.x;
    if (i < n_rows) {
        int s = index[i];
        unsigned p = atomicAdd(&g_cursor[s], 1u);
        g_rows[p] = i;
    }
}

// ---------------------------------------------------------------------------
// 7: gather-accumulate. One warp per segment; lane owns one float2 column.
//    4-row unroll for MLP (hides DRAM latency + TLB walks).
// ---------------------------------------------------------------------------
__global__ void gather_kernel(const float2* __restrict__ x2,
                              float2* __restrict__ out2, int n_seg) {
    int w    = (blockIdx.x * blockDim.x + threadIdx.x) >> 5;
    int lane = threadIdx.x & 31;
    if (w >= n_seg) return;

    unsigned start = g_offsets[w];
    unsigned cnt   = g_counts[w];

    float2 a0 = {0.f, 0.f}, a1 = {0.f, 0.f}, a2 = {0.f, 0.f}, a3 = {0.f, 0.f};
    unsigned r = 0;
    for (; r + 4 <= cnt; r += 4) {
        int i0 = g_rows[start + r + 0];
        int i1 = g_rows[start + r + 1];
        int i2 = g_rows[start + r + 2];
        int i3 = g_rows[start + r + 3];
        float2 v0 = x2[(size_t)i0 * 32 + lane];
        float2 v1 = x2[(size_t)i1 * 32 + lane];
        float2 v2 = x2[(size_t)i2 * 32 + lane];
        float2 v3 = x2[(size_t)i3 * 32 + lane];
        a0.x += v0.x; a0.y += v0.y;
        a1.x += v1.x; a1.y += v1.y;
        a2.x += v2.x; a2.y += v2.y;
        a3.x += v3.x; a3.y += v3.y;
    }
    for (; r < cnt; r++) {
        int i0 = g_rows[start + r];
        float2 v = x2[(size_t)i0 * 32 + lane];
        a0.x += v.x; a0.y += v.y;
    }

    float inv = 1.0f / fmaxf((float)cnt, 1.0f);
    float2 res;
    res.x = (a0.x + a1.x + a2.x + a3.x) * inv;
    res.y = (a0.y + a1.y + a2.y + a3.y) * inv;
    out2[(size_t)w * 32 + lane] = res;
}

// ---------------------------------------------------------------------------
extern "C" void kernel_launch(void* const* d_in, const int* in_sizes, int n_in,
                              void* d_out, int out_size) {
    const float2* x2    = (const float2*)d_in[0];
    const int*    index = (const int*)d_in[1];
    float2*       out2  = (float2*)d_out;

    int n_rows = in_sizes[1];        // len(index) == N
    int n_seg  = out_size / 64;      // D = 64

    int T = 256;
    int seg_blocks  = (n_seg  + T - 1) / T;
    int row_blocks  = (n_rows + T - 1) / T;
    int nblk_scan   = (n_seg + 1023) / 1024;   // <= 128 for n_seg <= 131072

    zero_counts<<<seg_blocks, T>>>(n_seg);
    hist_kernel<<<row_blocks, T>>>(index, n_rows);
    scan_blocks<<<nblk_scan, 256>>>(n_seg);
    scan_top<<<1, 256>>>(nblk_scan);
    finalize_offsets<<<seg_blocks, T>>>(n_seg);
    build_rows<<<row_blocks, T>>>(index, n_rows);

    long long gather_threads = (long long)n_seg * 32;
    int gather_blocks = (int)((gather_threads + T - 1) / T);
    gather_kernel<<<gather_blocks, T>>>(x2, out2, n_seg);
}